// round 2
// baseline (speedup 1.0000x reference)
#include <cuda_runtime.h>
#include <cuda_bf16.h>
#include <cstdint>

// ---------------- problem shape ----------------
static constexpr int B_ROWS = 16384;
static constexpr int C_ROWS = 4096;
static constexpr int KDIM   = 1024;

// ---------------- GEMM tiling ----------------
static constexpr int BM = 128;
static constexpr int BN = 128;
static constexpr int BK = 64;                 // bf16 elems per K-chunk
static constexpr int STAGES = 3;
static constexpr int KTILES = KDIM / BK;      // 16
static constexpr int KSTEPS = BK / 16;        // 4 mma k-steps per chunk

// padded smem rows: 64 + 8 halves -> 144B stride (conflict-free ldmatrix)
static constexpr int ROW_H   = BK + 8;        // 72 halves
static constexpr int TILE_B  = 128 * ROW_H * 2;   // 18432 bytes per (A or B) stage
static constexpr int OFF_B0  = STAGES * TILE_B;   // B stages after A stages
static constexpr int SMEM_BYTES = 2 * STAGES * TILE_B;  // 110592

// ---------------- device scratch (no cudaMalloc allowed) ----------------
__device__ __nv_bfloat16 g_featb[(size_t)B_ROWS * KDIM];
__device__ __nv_bfloat16 g_centb[(size_t)C_ROWS * KDIM];
__device__ float g_x2[B_ROWS];
__device__ float g_c2[C_ROWS];

// ---------------- PTX helpers ----------------
__device__ __forceinline__ uint32_t smem_u32(const void* p) {
    uint32_t a;
    asm("{ .reg .u64 t; cvta.to.shared.u64 t, %1; cvt.u32.u64 %0, t; }"
        : "=r"(a) : "l"(p));
    return a;
}

__device__ __forceinline__ void cp_async16(uint32_t s_addr, const void* g_addr) {
    asm volatile("cp.async.cg.shared.global [%0], [%1], 16;"
                 :: "r"(s_addr), "l"(g_addr) : "memory");
}
__device__ __forceinline__ void cp_commit() {
    asm volatile("cp.async.commit_group;" ::: "memory");
}
template <int N>
__device__ __forceinline__ void cp_wait() {
    asm volatile("cp.async.wait_group %0;" :: "n"(N) : "memory");
}

__device__ __forceinline__ void ldsm_x4(uint32_t& r0, uint32_t& r1, uint32_t& r2, uint32_t& r3,
                                        uint32_t addr) {
    asm volatile("ldmatrix.sync.aligned.m8n8.x4.shared.b16 {%0,%1,%2,%3}, [%4];"
                 : "=r"(r0), "=r"(r1), "=r"(r2), "=r"(r3) : "r"(addr));
}

__device__ __forceinline__ void mma16816(float* d, uint32_t a0, uint32_t a1, uint32_t a2,
                                         uint32_t a3, uint32_t b0, uint32_t b1) {
    asm volatile(
        "mma.sync.aligned.m16n8k16.row.col.f32.bf16.bf16.f32 "
        "{%0,%1,%2,%3}, {%4,%5,%6,%7}, {%8,%9}, {%0,%1,%2,%3};"
        : "+f"(d[0]), "+f"(d[1]), "+f"(d[2]), "+f"(d[3])
        : "r"(a0), "r"(a1), "r"(a2), "r"(a3), "r"(b0), "r"(b1));
}

// ---------------- prep: fp32 -> bf16 + row sum-of-squares ----------------
__global__ __launch_bounds__(256)
void prep_kernel(const float* __restrict__ in, __nv_bfloat16* __restrict__ outbf,
                 float* __restrict__ sq) {
    int row = blockIdx.x;
    int t = threadIdx.x;
    float4 v = reinterpret_cast<const float4*>(in)[(size_t)row * 256 + t];

    float s = fmaf(v.x, v.x, fmaf(v.y, v.y, fmaf(v.z, v.z, v.w * v.w)));
    #pragma unroll
    for (int o = 16; o > 0; o >>= 1) s += __shfl_xor_sync(0xFFFFFFFFu, s, o);
    __shared__ float ws[8];
    if ((t & 31) == 0) ws[t >> 5] = s;
    __syncthreads();
    if (t < 8) {
        float x = ws[t];
        #pragma unroll
        for (int o = 4; o > 0; o >>= 1) x += __shfl_xor_sync(0xFFu, x, o);
        if (t == 0) sq[row] = x;
    }

    union { __nv_bfloat162 h2[2]; uint2 u; } pk;
    pk.h2[0] = __floats2bfloat162_rn(v.x, v.y);
    pk.h2[1] = __floats2bfloat162_rn(v.z, v.w);
    reinterpret_cast<uint2*>(outbf)[(size_t)row * 256 + t] = pk.u;
}

// ---------------- main GEMM + fused distance epilogue ----------------
__global__ __launch_bounds__(256, 1)
void dist_gemm_kernel(const __nv_bfloat16* __restrict__ Abf,
                      const __nv_bfloat16* __restrict__ Bbf,
                      const float* __restrict__ x2,
                      const float* __restrict__ c2,
                      float* __restrict__ out) {
    extern __shared__ char smem[];
    const uint32_t sb = smem_u32(smem);
    const int tid = threadIdx.x;
    const int wid = tid >> 5;
    const int lane = tid & 31;

    // n-fast tile mapping for L2 reuse of the A (feat) tile across a wave
    const int nt = blockIdx.x & 31;           // 32 n-tiles
    const int mt = blockIdx.x >> 5;           // 128 m-tiles
    const int m_base = mt * BM;
    const int n_base = nt * BN;

    // cp.async load mapping: 8 x 16B chunks per thread per (A or B) stage
    // chunkid = tid + i*256 ; row = chunkid/8 ; c = chunkid%8
    auto load_stage = [&](int s, int kt) {
        const uint32_t sA = sb + s * TILE_B;
        const uint32_t sB = sb + OFF_B0 + s * TILE_B;
        const __nv_bfloat16* gA = Abf + (size_t)m_base * KDIM + kt * BK;
        const __nv_bfloat16* gB = Bbf + (size_t)n_base * KDIM + kt * BK;
        #pragma unroll
        for (int i = 0; i < 4; i++) {
            int cid = tid + i * 256;
            int row = cid >> 3, c = cid & 7;
            cp_async16(sA + row * (ROW_H * 2) + c * 16, gA + (size_t)row * KDIM + c * 8);
        }
        #pragma unroll
        for (int i = 0; i < 4; i++) {
            int cid = tid + i * 256;
            int row = cid >> 3, c = cid & 7;
            cp_async16(sB + row * (ROW_H * 2) + c * 16, gB + (size_t)row * KDIM + c * 8);
        }
    };

    // warp tiling: 2 (M) x 4 (N); each warp 64x32
    const int wm = wid >> 2;                  // 0..1
    const int wn = wid & 3;                   // 0..3

    float acc[4][4][4];                       // [mtile][ntile][frag]
    #pragma unroll
    for (int i = 0; i < 4; i++)
        #pragma unroll
        for (int j = 0; j < 4; j++)
            #pragma unroll
            for (int f = 0; f < 4; f++) acc[i][j][f] = 0.0f;

    // ldmatrix per-lane addresses (stage-relative, bytes)
    // A x4: lanes 0-7 rows m..m+7 @k0 | 8-15 rows m+8.. @k0 | 16-23 rows m @k0+8 | 24-31 m+8 @k0+8
    const int a_row_l = (lane & 15);          // row within 16
    const int a_koff  = (lane >> 4) * 8;      // 0 or 8 halves
    // B x4 (pair of ntiles): lanes<16 -> ntile 2j, >=16 -> 2j+1 ; (lane>>3)&1 -> k group
    const int b_row_l = (lane & 7) + ((lane >> 4) << 4);  // n offset within 32-wide pair region? computed per j below
    const int b_koff  = ((lane >> 3) & 1) * 8;

    // prologue: fill 3 stages
    load_stage(0, 0); cp_commit();
    load_stage(1, 1); cp_commit();
    load_stage(2, 2); cp_commit();

    #pragma unroll 1
    for (int kt = 0; kt < KTILES; kt++) {
        const int s = kt % STAGES;
        cp_wait<2>();
        __syncthreads();

        const uint32_t sA = sb + s * TILE_B;
        const uint32_t sB = sb + OFF_B0 + s * TILE_B;

        #pragma unroll
        for (int kk = 0; kk < KSTEPS; kk++) {
            const int k0 = kk * 16;
            // load A frags (4 mtiles)
            uint32_t af[4][4];
            #pragma unroll
            for (int i = 0; i < 4; i++) {
                int row = wm * 64 + i * 16 + a_row_l;
                uint32_t addr = sA + row * (ROW_H * 2) + (k0 + a_koff) * 2;
                ldsm_x4(af[i][0], af[i][1], af[i][2], af[i][3], addr);
            }
            // load B frags (4 ntiles via 2 x4-ldmatrix)
            uint32_t bf[4][2];
            #pragma unroll
            for (int j = 0; j < 2; j++) {
                int n = wn * 32 + (2 * j + (lane >> 4)) * 8 + (lane & 7);
                uint32_t addr = sB + n * (ROW_H * 2) + (k0 + b_koff) * 2;
                uint32_t r0, r1, r2, r3;
                ldsm_x4(r0, r1, r2, r3, addr);
                bf[2 * j][0] = r0; bf[2 * j][1] = r1;
                bf[2 * j + 1][0] = r2; bf[2 * j + 1][1] = r3;
            }
            // 16 HMMA
            #pragma unroll
            for (int i = 0; i < 4; i++)
                #pragma unroll
                for (int j = 0; j < 4; j++)
                    mma16816(acc[i][j], af[i][0], af[i][1], af[i][2], af[i][3],
                             bf[j][0], bf[j][1]);
        }

        __syncthreads();
        if (kt + STAGES < KTILES) load_stage(s, kt + STAGES);
        cp_commit();
    }
    (void)b_row_l;

    // ---------------- epilogue: dist = x2[m] + c2[n] - 2*acc ----------------
    const int g = lane >> 2;          // row group 0..7
    const int q = lane & 3;           // col quad
    #pragma unroll
    for (int i = 0; i < 4; i++) {
        const int r0 = m_base + wm * 64 + i * 16 + g;
        const int r1 = r0 + 8;
        const float x0 = __ldg(&x2[r0]);
        const float x1 = __ldg(&x2[r1]);
        #pragma unroll
        for (int j = 0; j < 4; j++) {
            const int col = n_base + wn * 32 + j * 8 + q * 2;
            const float cA = __ldg(&c2[col]);
            const float cB = __ldg(&c2[col + 1]);
            float2 v0, v1;
            v0.x = fmaf(-2.0f, acc[i][j][0], x0 + cA);
            v0.y = fmaf(-2.0f, acc[i][j][1], x0 + cB);
            v1.x = fmaf(-2.0f, acc[i][j][2], x1 + cA);
            v1.y = fmaf(-2.0f, acc[i][j][3], x1 + cB);
            *reinterpret_cast<float2*>(&out[(size_t)r0 * C_ROWS + col]) = v0;
            *reinterpret_cast<float2*>(&out[(size_t)r1 * C_ROWS + col]) = v1;
        }
    }
}

// ---------------- host launch ----------------
extern "C" void kernel_launch(void* const* d_in, const int* in_sizes, int n_in,
                              void* d_out, int out_size) {
    (void)in_sizes; (void)n_in; (void)out_size;
    const float* feat = (const float*)d_in[0];
    const float* cent = (const float*)d_in[1];
    float* out = (float*)d_out;

    void *p_fb = nullptr, *p_cb = nullptr, *p_x2 = nullptr, *p_c2 = nullptr;
    cudaGetSymbolAddress(&p_fb, g_featb);
    cudaGetSymbolAddress(&p_cb, g_centb);
    cudaGetSymbolAddress(&p_x2, g_x2);
    cudaGetSymbolAddress(&p_c2, g_c2);

    prep_kernel<<<B_ROWS, 256>>>(feat, (__nv_bfloat16*)p_fb, (float*)p_x2);
    prep_kernel<<<C_ROWS, 256>>>(cent, (__nv_bfloat16*)p_cb, (float*)p_c2);

    cudaFuncSetAttribute(dist_gemm_kernel,
                         cudaFuncAttributeMaxDynamicSharedMemorySize, SMEM_BYTES);

    int grid = (B_ROWS / BM) * (C_ROWS / BN);   // 4096
    dist_gemm_kernel<<<grid, 256, SMEM_BYTES>>>(
        (const __nv_bfloat16*)p_fb, (const __nv_bfloat16*)p_cb,
        (const float*)p_x2, (const float*)p_c2, out);
}